// round 16
// baseline (speedup 1.0000x reference)
#include <cuda_runtime.h>
#include <math.h>

#define NITEM 40000
#define NUSER 10000
#define NN    50000
#define DD    128
#define DXX   64
#define EE    400000
#define BB    4096
#define MMOD  4

// ---------------- scratch (device globals; no runtime allocation) ----------------
__device__ float g_x  [MMOD * NN * DD];
__device__ float g_xt [MMOD * NN * DD];
__device__ float g_agg[MMOD * NN * DD];
__device__ float g_xh [MMOD * NN * DXX];
__device__ float g_reps[MMOD * NN * DXX];
__device__ float g_w  [MMOD * EE];
__device__ float g_dinv[NN];
__device__ float g_deg [NN];
__device__ float g_kmod[MMOD * DXX];
__device__ float g_kp[MMOD * DXX];
__device__ float g_vp[MMOD * DXX];
// CSR by dst (built once per call; dst list is m-independent)
__device__ int g_csr_cnt[NN];
__device__ int g_csr_off[NN + 1];
__device__ int g_csr_cur[NN];
__device__ int g_csr_eid[EE];

__device__ __forceinline__ float lrelu(float x) { return x > 0.f ? x : 0.01f * x; }

// ---------------- tf32 helpers ----------------
__device__ __forceinline__ uint2 tf32split(float v) {
    unsigned b, s;
    asm("cvt.rna.tf32.f32 %0, %1;" : "=r"(b) : "f"(v));
    float r = v - __uint_as_float(b);
    asm("cvt.rna.tf32.f32 %0, %1;" : "=r"(s) : "f"(r));
    return make_uint2(b, s);
}

__device__ __forceinline__ void mma_tf32(float* c, const unsigned* a, const unsigned* b) {
    asm volatile(
        "mma.sync.aligned.m16n8k8.row.col.f32.tf32.tf32.f32 "
        "{%0,%1,%2,%3}, {%4,%5,%6,%7}, {%8,%9}, {%0,%1,%2,%3};"
        : "+f"(c[0]), "+f"(c[1]), "+f"(c[2]), "+f"(c[3])
        : "r"(a[0]), "r"(a[1]), "r"(a[2]), "r"(a[3]), "r"(b[0]), "r"(b[1]));
}

// ---------------- small utility kernels ----------------
__global__ void zero_n_k(float* p, int n) {
    int i = blockIdx.x * blockDim.x + threadIdx.x;
    if (i < n) p[i] = 0.f;
}

__global__ void deg_accum_k(const int* __restrict__ src) {
    int e = blockIdx.x * blockDim.x + threadIdx.x;
    if (e < EE) atomicAdd(&g_deg[src[e]], 1.0f);
}

__global__ void make_dinv_k() {
    int n = blockIdx.x * blockDim.x + threadIdx.x;
    if (n < NN) {
        float d = g_deg[n];
        g_dinv[n] = d > 0.f ? rsqrtf(d) : 0.f;
    }
}

// ---------------- CSR build (dst-sorted edge lists) ----------------
__global__ void csr_zero_k() {
    int i = blockIdx.x * blockDim.x + threadIdx.x;
    if (i < NN) g_csr_cnt[i] = 0;
}

__global__ void csr_count_k(const int* __restrict__ dst) {
    int e = blockIdx.x * blockDim.x + threadIdx.x;
    if (e < EE) atomicAdd(&g_csr_cnt[dst[e]], 1);
}

// single-block exclusive scan of g_csr_cnt -> g_csr_off  (1024 threads)
__global__ void csr_scan_k() {
    __shared__ int warp_sums[32];
    __shared__ int s_carry;
    int tid = threadIdx.x, lane = tid & 31, wid = tid >> 5;
    if (tid == 0) s_carry = 0;
    __syncthreads();
    for (int base = 0; base < NN; base += 1024) {
        int i = base + tid;
        int v = (i < NN) ? g_csr_cnt[i] : 0;
        int x = v;
        #pragma unroll
        for (int o = 1; o < 32; o <<= 1) {
            int y = __shfl_up_sync(0xffffffffu, x, o);
            if (lane >= o) x += y;
        }
        if (lane == 31) warp_sums[wid] = x;
        __syncthreads();
        if (wid == 0) {
            int s = warp_sums[lane];
            #pragma unroll
            for (int o = 1; o < 32; o <<= 1) {
                int y = __shfl_up_sync(0xffffffffu, s, o);
                if (lane >= o) s += y;
            }
            warp_sums[lane] = s;
        }
        __syncthreads();
        int warp_off = (wid == 0) ? 0 : warp_sums[wid - 1];
        int excl = s_carry + warp_off + x - v;
        if (i < NN) g_csr_off[i] = excl;
        if (i == NN - 1) g_csr_off[NN] = excl + v;
        __syncthreads();
        if (tid == 1023) s_carry += warp_sums[31];
        __syncthreads();
    }
}

__global__ void csr_copycur_k() {
    int i = blockIdx.x * blockDim.x + threadIdx.x;
    if (i < NN) g_csr_cur[i] = g_csr_off[i];
}

__global__ void csr_scatter_k(const int* __restrict__ dst) {
    int e = blockIdx.x * blockDim.x + threadIdx.x;
    if (e < EE) {
        int pos = atomicAdd(&g_csr_cur[dst[e]], 1);
        g_csr_eid[pos] = e;
    }
}

// ---------------- node normalization kernels ----------------
__global__ void rownorm_x_k(const float* __restrict__ feats) {
    int gt = blockIdx.x * blockDim.x + threadIdx.x;
    int r = gt >> 5, lane = gt & 31;
    int m = blockIdx.y;
    if (r >= NN) return;
    float* xrow = g_x + ((size_t)m * NN + r) * DD;
    const float* srcp = (r < NITEM)
        ? feats + ((size_t)m * NITEM + r) * DD
        : xrow;
    float4 v = *(reinterpret_cast<const float4*>(srcp) + lane);
    float ss = v.x * v.x + v.y * v.y + v.z * v.z + v.w * v.w;
    #pragma unroll
    for (int o = 16; o; o >>= 1) ss += __shfl_xor_sync(0xffffffffu, ss, o);
    float sc = 1.0f / fmaxf(sqrtf(ss), 1e-12f);
    v.x *= sc; v.y *= sc; v.z *= sc; v.w *= sc;
    *(reinterpret_cast<float4*>(xrow) + lane) = v;
}

__global__ void rownorm_agg_k(const float* __restrict__ convb) {
    int gt = blockIdx.x * blockDim.x + threadIdx.x;
    int r = gt >> 5, lane = gt & 31;
    int m = blockIdx.y;
    if (r >= NN) return;
    float* row = g_agg + ((size_t)m * NN + r) * DD;
    float4 v = *(reinterpret_cast<float4*>(row) + lane);
    float4 b = *(reinterpret_cast<const float4*>(convb + m * DD) + lane);
    v.x += b.x; v.y += b.y; v.z += b.z; v.w += b.w;
    float ss = v.x * v.x + v.y * v.y + v.z * v.z + v.w * v.w;
    #pragma unroll
    for (int o = 16; o; o >>= 1) ss += __shfl_xor_sync(0xffffffffu, ss, o);
    float sc = 1.0f / fmaxf(sqrtf(ss), 1e-12f);
    v.x = lrelu(v.x * sc); v.y = lrelu(v.y * sc);
    v.z = lrelu(v.z * sc); v.w = lrelu(v.w * sc);
    *(reinterpret_cast<float4*>(row) + lane) = v;
}

// ---------------- tensor-core GEMM (3xTF32, split-at-stage), grid.y = m -------------
template<int TN, bool BT, int EPI>
__global__ __launch_bounds__(256)
void mma_gemm_k(const float* __restrict__ A, long As_,
                const float* __restrict__ B, long Bs_,
                const float* __restrict__ bias, long biasS,
                const float* __restrict__ add, long addS,
                float* __restrict__ C, long Cs_, int rows) {
    constexpr int NPW = TN / 16;
    __shared__ uint2 As[128][20];
    __shared__ uint2 Bs[TN][20];

    int m = blockIdx.y;
    A += (size_t)m * As_;
    B += (size_t)m * Bs_;
    if (EPI != 0) bias += (size_t)m * biasS;
    if (EPI >= 2) add += (size_t)m * addS;
    C += (size_t)m * Cs_;

    int tid = threadIdx.x;
    int warp = tid >> 5, lane = tid & 31;
    int warp_m = warp & 3, warp_n = warp >> 2;
    int colb = warp_n * (TN / 2);
    int row0 = blockIdx.x * 128;
    int gid = lane >> 2, tig = lane & 3;

    float acc[2][NPW][4];
    #pragma unroll
    for (int mt = 0; mt < 2; mt++)
        #pragma unroll
        for (int nt = 0; nt < NPW; nt++)
            #pragma unroll
            for (int j = 0; j < 4; j++) acc[mt][nt][j] = 0.f;

    for (int k0 = 0; k0 < 128; k0 += 16) {
        #pragma unroll
        for (int it = 0; it < 2; it++) {
            int i = tid + it * 256;
            int r = i >> 2, seg = i & 3;
            int gr = row0 + r;
            float4 v = make_float4(0.f, 0.f, 0.f, 0.f);
            if (gr < rows) v = *reinterpret_cast<const float4*>(A + (size_t)gr * 128 + k0 + seg * 4);
            As[r][seg * 4 + 0] = tf32split(v.x);
            As[r][seg * 4 + 1] = tf32split(v.y);
            As[r][seg * 4 + 2] = tf32split(v.z);
            As[r][seg * 4 + 3] = tf32split(v.w);
        }
        if (BT) {
            #pragma unroll
            for (int it = 0; it < TN / 64; it++) {
                int i = tid + it * 256;
                int r = i >> 2, seg = i & 3;
                float4 v = *reinterpret_cast<const float4*>(B + (size_t)r * 128 + k0 + seg * 4);
                Bs[r][seg * 4 + 0] = tf32split(v.x);
                Bs[r][seg * 4 + 1] = tf32split(v.y);
                Bs[r][seg * 4 + 2] = tf32split(v.z);
                Bs[r][seg * 4 + 3] = tf32split(v.w);
            }
        } else {
            #pragma unroll
            for (int it = 0; it < TN / 64; it++) {
                int i = tid + it * 256;
                int k = i / (TN / 4), nseg = i % (TN / 4);
                float4 v = *reinterpret_cast<const float4*>(B + (size_t)(k0 + k) * TN + nseg * 4);
                Bs[nseg * 4 + 0][k] = tf32split(v.x);
                Bs[nseg * 4 + 1][k] = tf32split(v.y);
                Bs[nseg * 4 + 2][k] = tf32split(v.z);
                Bs[nseg * 4 + 3][k] = tf32split(v.w);
            }
        }
        __syncthreads();

        #pragma unroll
        for (int kk = 0; kk < 16; kk += 8) {
            int kc = kk + tig;
            unsigned abig[2][4], asml[2][4];
            #pragma unroll
            for (int mt = 0; mt < 2; mt++) {
                int mr = warp_m * 32 + mt * 16 + gid;
                uint2 a0 = As[mr    ][kc    ];
                uint2 a1 = As[mr + 8][kc    ];
                uint2 a2 = As[mr    ][kc + 4];
                uint2 a3 = As[mr + 8][kc + 4];
                abig[mt][0] = a0.x; asml[mt][0] = a0.y;
                abig[mt][1] = a1.x; asml[mt][1] = a1.y;
                abig[mt][2] = a2.x; asml[mt][2] = a2.y;
                abig[mt][3] = a3.x; asml[mt][3] = a3.y;
            }
            #pragma unroll
            for (int nt = 0; nt < NPW; nt++) {
                int n = colb + nt * 8 + gid;
                uint2 b0 = Bs[n][kc    ];
                uint2 b1 = Bs[n][kc + 4];
                unsigned bbig[2] = { b0.x, b1.x };
                unsigned bsml[2] = { b0.y, b1.y };
                #pragma unroll
                for (int mt = 0; mt < 2; mt++) {
                    mma_tf32(acc[mt][nt], asml[mt], bbig);
                    mma_tf32(acc[mt][nt], abig[mt], bsml);
                    mma_tf32(acc[mt][nt], abig[mt], bbig);
                }
            }
        }
        __syncthreads();
    }

    #pragma unroll
    for (int mt = 0; mt < 2; mt++) {
        #pragma unroll
        for (int half = 0; half < 2; half++) {
            int r = row0 + warp_m * 32 + mt * 16 + gid + half * 8;
            if (r >= rows) continue;
            #pragma unroll
            for (int nt = 0; nt < NPW; nt++) {
                int c = colb + nt * 8 + tig * 2;
                float v0 = acc[mt][nt][half * 2 + 0];
                float v1 = acc[mt][nt][half * 2 + 1];
                if (EPI == 1) {
                    v0 = tanhf(v0 + bias[c]);
                    v1 = tanhf(v1 + bias[c + 1]);
                } else if (EPI == 2) {
                    v0 = lrelu(v0 + bias[c])     + add[(size_t)r * TN + c];
                    v1 = lrelu(v1 + bias[c + 1]) + add[(size_t)r * TN + c + 1];
                } else if (EPI == 3) {
                    v0 = lrelu(v0 + bias[c]     + add[(size_t)r * TN + c]);
                    v1 = lrelu(v1 + bias[c + 1] + add[(size_t)r * TN + c + 1]);
                }
                *reinterpret_cast<float2*>(C + (size_t)r * TN + c) = make_float2(v0, v1);
            }
        }
    }
}

// ---------------- edge kernels ----------------
// pass1: per-edge logit w (warp per edge; grid.y = m). No atomics.
__global__ void edge_pass1_k(const int* __restrict__ src, const int* __restrict__ dst) {
    int gt = blockIdx.x * blockDim.x + threadIdx.x;
    int e = gt >> 5, lane = gt & 31;
    int m = blockIdx.y;
    if (e >= EE) return;
    int s = src[e], d = dst[e];
    const float* xt = g_xt + (size_t)m * NN * DD;
    float4 xs = *reinterpret_cast<const float4*>(xt + (size_t)s * DD + lane * 4);
    float4 xd = *reinterpret_cast<const float4*>(xt + (size_t)d * DD + lane * 4);
    float p = xd.x * lrelu(xs.x) + xd.y * lrelu(xs.y) + xd.z * lrelu(xs.z) + xd.w * lrelu(xs.w);
    #pragma unroll
    for (int o = 16; o; o >>= 1) p += __shfl_down_sync(0xffffffffu, p, o);
    if (lane == 0) {
        float ip = p;
        float di = g_dinv[s];
        g_w[(size_t)m * EE + e] = ip * (1.0f / (1.0f + expf(-di * ip)));
    }
}

// per-dst segment softmax + aggregation (warp per dst; grid.y = m). No atomics.
__global__ void agg_csr_k(const int* __restrict__ src) {
    int gt = blockIdx.x * blockDim.x + threadIdx.x;
    int d = gt >> 5, lane = gt & 31;
    int m = blockIdx.y;
    if (d >= NN) return;
    int beg = g_csr_off[d], end = g_csr_off[d + 1];
    const float* wv = g_w + (size_t)m * EE;

    float mx = -INFINITY;
    for (int i = beg + lane; i < end; i += 32) mx = fmaxf(mx, wv[g_csr_eid[i]]);
    #pragma unroll
    for (int o = 16; o; o >>= 1) mx = fmaxf(mx, __shfl_xor_sync(0xffffffffu, mx, o));

    float sum = 0.f;
    for (int i = beg + lane; i < end; i += 32) sum += expf(wv[g_csr_eid[i]] - mx);
    #pragma unroll
    for (int o = 16; o; o >>= 1) sum += __shfl_xor_sync(0xffffffffu, sum, o);
    float inv = 1.0f / (sum + 1e-16f);

    const float* xt = g_xt + (size_t)m * NN * DD;
    float4 acc = make_float4(0.f, 0.f, 0.f, 0.f);
    for (int i = beg; i < end; i++) {
        int e = g_csr_eid[i];
        float att = expf(wv[e] - mx) * inv;
        float4 xs = *reinterpret_cast<const float4*>(xt + (size_t)src[e] * DD + lane * 4);
        acc.x += att * xs.x; acc.y += att * xs.y;
        acc.z += att * xs.z; acc.w += att * xs.w;
    }
    *reinterpret_cast<float4*>(g_agg + (size_t)m * NN * DD + (size_t)d * DD + lane * 4) = acc;
}

// ---------------- head kernels ----------------
__global__ void rep_mean_k(float* __restrict__ rep_out) {
    int i = blockIdx.x * blockDim.x + threadIdx.x;
    const int S = NN * DXX;
    if (i < S)
        rep_out[i] = 0.25f * (g_reps[i] + g_reps[i + S] + g_reps[i + 2 * S] + g_reps[i + 3 * S]);
}

__global__ void kmod_accum_k(const int* __restrict__ pitems) {
    int m = blockIdx.y;
    int base = blockIdx.x * 64;
    int t = threadIdx.x;
    int c = t & 63, sub = t >> 6;
    float s = 0.f;
    for (int i = sub; i < 64; i += 4) {
        int idx = pitems[base + i];
        s += g_reps[((size_t)m * NN + idx) * DXX + c];
    }
    __shared__ float part[64];
    if (t < 64) part[t] = 0.f;
    __syncthreads();
    atomicAdd(&part[c], s);
    __syncthreads();
    if (t < 64) atomicAdd(&g_kmod[m * DXX + t], part[t]);
}

__global__ void proj_k(const float* __restrict__ kW, const float* __restrict__ vW) {
    int t = threadIdx.x;
    __shared__ float km[MMOD * DXX];
    km[t] = g_kmod[t] * (1.0f / BB);
    __syncthreads();
    int m = t / DXX, c = t % DXX;
    float a = 0.f, b = 0.f;
    #pragma unroll
    for (int k = 0; k < DXX; k++) {
        float x = km[m * DXX + k];
        a += x * kW[c * DXX + k];
        b += x * vW[c * DXX + k];
    }
    g_kp[t] = a;
    g_vp[t] = b;
}

__global__ void finalize_k(const float* __restrict__ rep,
                           const int* __restrict__ un, const int* __restrict__ pi,
                           const int* __restrict__ ni,
                           const float* __restrict__ qW,
                           const float* __restrict__ mpW1, const float* __restrict__ mpb1,
                           const float* __restrict__ mpW2, const float* __restrict__ mpb2,
                           float* __restrict__ out_pos, float* __restrict__ out_neg,
                           float* __restrict__ out_price) {
    int b = blockIdx.x, t = threadIdx.x;
    __shared__ float su[DXX], sp[DXX], sn[DXX], satt[DXX], lg[4], red[DXX];
    int u = un[b], p = pi[b], n = ni[b];
    su[t] = rep[(size_t)u * DXX + t];
    sp[t] = rep[(size_t)p * DXX + t];
    sn[t] = rep[(size_t)n * DXX + t];
    if (t < 4) lg[t] = 0.f;
    __syncthreads();
    float q = 0.f;
    #pragma unroll
    for (int k = 0; k < DXX; k++) q += su[k] * qW[t * DXX + k];
    #pragma unroll
    for (int j = 0; j < 4; j++) atomicAdd(&lg[j], q * g_kp[j * DXX + t]);
    __syncthreads();
    float l[4], mx = -1e30f;
    #pragma unroll
    for (int j = 0; j < 4; j++) { l[j] = lg[j] * 0.125f; mx = fmaxf(mx, l[j]); }
    float ps = 0.f;
    #pragma unroll
    for (int j = 0; j < 4; j++) { l[j] = expf(l[j] - mx); ps += l[j]; }
    float inv = 1.0f / ps;
    float att = 0.f;
    #pragma unroll
    for (int j = 0; j < 4; j++) att += (l[j] * inv) * g_vp[j * DXX + t];
    satt[t] = att;

    red[t] = att * sp[t];
    __syncthreads();
    for (int s2 = 32; s2 > 0; s2 >>= 1) { if (t < s2) red[t] += red[t + s2]; __syncthreads(); }
    if (t == 0) out_pos[b] = red[0];
    __syncthreads();
    red[t] = att * sn[t];
    __syncthreads();
    for (int s2 = 32; s2 > 0; s2 >>= 1) { if (t < s2) red[t] += red[t + s2]; __syncthreads(); }
    if (t == 0) out_neg[b] = red[0];
    __syncthreads();

    float h = 0.f;
    #pragma unroll
    for (int k = 0; k < DXX; k++) h += satt[k] * mpW1[t * 2 * DXX + k];
    #pragma unroll
    for (int k = 0; k < DXX; k++) h += sp[k] * mpW1[t * 2 * DXX + DXX + k];
    h = lrelu(h + mpb1[t]);
    red[t] = h * mpW2[t];
    __syncthreads();
    for (int s2 = 32; s2 > 0; s2 >>= 1) { if (t < s2) red[t] += red[t + s2]; __syncthreads(); }
    if (t == 0) out_price[b] = red[0] + mpb2[0];
}

// ---------------- launcher ----------------
extern "C" void kernel_launch(void* const* d_in, const int* in_sizes, int n_in,
                              void* d_out, int out_size) {
    const float* feats   = (const float*)d_in[0];
    const float* uf      = (const float*)d_in[1];
    const float* userW   = (const float*)d_in[2];
    const float* userb   = (const float*)d_in[3];
    const float* convW   = (const float*)d_in[4];
    const float* convb   = (const float*)d_in[5];
    const float* lin1W   = (const float*)d_in[6];
    const float* lin1b   = (const float*)d_in[7];
    const float* g1W     = (const float*)d_in[8];
    const float* g1b     = (const float*)d_in[9];
    const float* id_emb  = (const float*)d_in[10];
    const float* qW      = (const float*)d_in[11];
    const float* kW      = (const float*)d_in[12];
    const float* vW      = (const float*)d_in[13];
    const float* mpW1    = (const float*)d_in[14];
    const float* mpb1    = (const float*)d_in[15];
    const float* mpW2    = (const float*)d_in[16];
    const float* mpb2    = (const float*)d_in[17];
    const int*   eidx    = (const int*)d_in[18];
    const int*   unodes  = (const int*)d_in[19];
    const int*   pitems  = (const int*)d_in[20];
    const int*   nitems  = (const int*)d_in[21];
    float* out = (float*)d_out;

    const int* src = eidx;
    const int* dst = eidx + EE;

    float *px, *pxt, *pagg, *pxh, *preps, *pkmod, *pdeg;
    cudaGetSymbolAddress((void**)&px,    g_x);
    cudaGetSymbolAddress((void**)&pxt,   g_xt);
    cudaGetSymbolAddress((void**)&pagg,  g_agg);
    cudaGetSymbolAddress((void**)&pxh,   g_xh);
    cudaGetSymbolAddress((void**)&preps, g_reps);
    cudaGetSymbolAddress((void**)&pkmod, g_kmod);
    cudaGetSymbolAddress((void**)&pdeg,  g_deg);

    float* rep_out   = out + 2 * BB;
    float* price_out = out + 2 * BB + (size_t)NN * DXX;

    const long SND = (long)NN * DD;
    const long SNX = (long)NN * DXX;

    // ---- degrees (src-side) + dst-CSR build, shared across modalities ----
    zero_n_k<<<(NN + 255) / 256, 256>>>(pdeg, NN);
    deg_accum_k<<<(EE + 255) / 256, 256>>>(src);
    make_dinv_k<<<(NN + 255) / 256, 256>>>();
    csr_zero_k<<<(NN + 255) / 256, 256>>>();
    csr_count_k<<<(EE + 255) / 256, 256>>>(dst);
    csr_scan_k<<<1, 1024>>>();
    csr_copycur_k<<<(NN + 255) / 256, 256>>>();
    csr_scatter_k<<<(EE + 255) / 256, 256>>>(dst);

    // ---- batched over all 4 modalities (grid.y = m) ----
    mma_gemm_k<128, true, 1><<<dim3((NUSER + 127) / 128, MMOD), 256>>>(
        uf, 0, userW, (long)DD * DD, userb, DD, nullptr, 0,
        px + (size_t)NITEM * DD, SND, NUSER);
    rownorm_x_k<<<dim3(NN * 32 / 256, MMOD), 256>>>(feats);
    mma_gemm_k<128, false, 0><<<dim3((NN + 127) / 128, MMOD), 256>>>(
        px, SND, convW, (long)DD * DD, nullptr, 0, nullptr, 0,
        pxt, SND, NN);
    mma_gemm_k<64, true, 2><<<dim3((NN + 127) / 128, MMOD), 256>>>(
        px, SND, lin1W, (long)DXX * DD, lin1b, DXX, id_emb, 0,
        pxh, SNX, NN);
    // edge attention: logits, then atomic-free per-dst softmax+aggregate
    edge_pass1_k<<<dim3(EE * 32 / 256, MMOD), 256>>>(src, dst);
    agg_csr_k<<<dim3((NN * 32 + 255) / 256, MMOD), 256>>>(src);
    rownorm_agg_k<<<dim3(NN * 32 / 256, MMOD), 256>>>(convb);
    mma_gemm_k<64, true, 3><<<dim3((NN + 127) / 128, MMOD), 256>>>(
        pagg, SND, g1W, (long)DXX * DD, g1b, DXX, pxh, SNX,
        preps, SNX, NN);

    // ---- head ----
    rep_mean_k<<<(NN * DXX + 255) / 256, 256>>>(rep_out);
    zero_n_k<<<1, 256>>>(pkmod, MMOD * DXX);
    kmod_accum_k<<<dim3(BB / 64, MMOD), 256>>>(pitems);
    proj_k<<<1, 256>>>(kW, vW);
    finalize_k<<<BB, 64>>>(rep_out, unodes, pitems, nitems, qW,
                           mpW1, mpb1, mpW2, mpb2,
                           out, out + BB, price_out);
}